// round 6
// baseline (speedup 1.0000x reference)
#include <cuda_runtime.h>
#include <math_constants.h>
#include <stdint.h>

#define BATCH 8
#define CH 256
#define HH 128
#define WW 128
#define HWSZ 16384
#define NPTS 500
#define NPAD 512
#define NHID 16

typedef unsigned long long u64;

// ---------------- scratch ----------------
__device__ float g_score[BATCH * HWSZ];
__device__ float g_spart[8 * BATCH * HWSZ];
__device__ int   g_idx[BATCH * NPTS];
__device__ float g_vmt [BATCH * CH * NPAD];   // v_main transposed [b][c][n], zero-padded
__device__ float g_vat [BATCH * CH * NPAD];   // v_aux  transposed [b][c][n]
__device__ float g_vaux[BATCH * NPTS * CH];   // v_aux row-major [b][n][c]

// ---------------- f32x2 helpers ----------------
__device__ __forceinline__ u64 pk2(float x, float y) {
    u64 d; asm("mov.b64 %0, {%1, %2};" : "=l"(d) : "f"(x), "f"(y)); return d;
}
__device__ __forceinline__ void upk2(float& x, float& y, u64 d) {
    asm("mov.b64 {%0, %1}, %2;" : "=f"(x), "=f"(y) : "l"(d));
}
__device__ __forceinline__ u64 f2fma(u64 a, u64 b, u64 c) {
    u64 d; asm("fma.rn.f32x2 %0, %1, %2, %3;" : "=l"(d) : "l"(a), "l"(b), "l"(c)); return d;
}
__device__ __forceinline__ u64 f2add(u64 a, u64 b) {
    u64 d; asm("add.rn.f32x2 %0, %1, %2;" : "=l"(d) : "l"(a), "l"(b)); return d;
}

// ================= kernel 1: fused copy + scorer partials (round-3/5 version) =================
__global__ void k1_copy_score(const float* __restrict__ xm,
                              const float* __restrict__ sw,
                              float* __restrict__ out) {
    __shared__ float s_w[32];
    int t = threadIdx.x, chunk = blockIdx.y;
    if (t < 32) s_w[t] = sw[chunk * 32 + t];
    __syncthreads();

    int gp = (blockIdx.x * 256 + t) * 4;
    int b  = gp >> 14;
    int hw = gp & (HWSZ - 1);
    const float4* src = reinterpret_cast<const float4*>(xm + (size_t)(b * CH + chunk * 32) * HWSZ + hw);
    float4*       dst = reinterpret_cast<float4*>(out + (size_t)(b * CH + chunk * 32) * HWSZ + hw);

    float a0 = 0.f, a1 = 0.f, a2 = 0.f, a3 = 0.f;
    #pragma unroll 8
    for (int c = 0; c < 32; ++c) {
        float4 v = src[c * (HWSZ / 4)];
        dst[c * (HWSZ / 4)] = v;
        float w = s_w[c];
        a0 += v.x * w; a1 += v.y * w; a2 += v.z * w; a3 += v.w * w;
    }
    *reinterpret_cast<float4*>(g_spart + (size_t)chunk * BATCH * HWSZ + gp) =
        make_float4(a0, a1, a2, a3);
}

__global__ void k1b_reduce() {
    int i = (blockIdx.x * 256 + threadIdx.x) * 4;
    float4 s = make_float4(0.f, 0.f, 0.f, 0.f);
    #pragma unroll
    for (int ch = 0; ch < 8; ++ch) {
        float4 v = *reinterpret_cast<const float4*>(g_spart + (size_t)ch * BATCH * HWSZ + i);
        s.x += v.x; s.y += v.y; s.z += v.z; s.w += v.w;
    }
    *reinterpret_cast<float4*>(g_score + i) = s;
}

// ================= kernel 2: exact top-500 per batch via radix select =================
__global__ void k2_topk() {
    __shared__ unsigned hist[256];
    __shared__ unsigned sh_pref;
    __shared__ int sh_k;
    __shared__ int cntGT, eqcnt;
    __shared__ int eqbuf[1024];

    int b = blockIdx.x, t = threadIdx.x, bd = blockDim.x;
    const float* sc = g_score + b * HWSZ;

    unsigned prefix = 0;
    int k = NPTS;
    for (int byte = 3; byte >= 0; --byte) {
        if (t < 256) hist[t] = 0;
        __syncthreads();
        int shamt = byte * 8;
        for (int i = t; i < HWSZ; i += bd) {
            unsigned u = __float_as_uint(sc[i]);
            u = (u & 0x80000000u) ? ~u : (u | 0x80000000u);
            bool m = (byte == 3) || ((u >> (shamt + 8)) == prefix);
            if (m) atomicAdd(&hist[(u >> shamt) & 255u], 1u);
        }
        __syncthreads();
        if (t == 0) {
            int cum = 0, bin;
            for (bin = 255; bin >= 0; --bin) {
                int h = (int)hist[bin];
                if (cum + h >= k) break;
                cum += h;
            }
            if (bin < 0) bin = 0;
            sh_pref = (prefix << 8) | (unsigned)bin;
            sh_k = k - cum;
        }
        __syncthreads();
        prefix = sh_pref; k = sh_k;
        __syncthreads();
    }
    unsigned T = prefix;
    if (t == 0) { cntGT = 0; eqcnt = 0; }
    __syncthreads();
    for (int i = t; i < HWSZ; i += bd) {
        unsigned u = __float_as_uint(sc[i]);
        u = (u & 0x80000000u) ? ~u : (u | 0x80000000u);
        if (u > T) {
            int p = atomicAdd(&cntGT, 1);
            if (p < NPTS) g_idx[b * NPTS + p] = i;
        } else if (u == T) {
            int e = atomicAdd(&eqcnt, 1);
            if (e < 1024) eqbuf[e] = i;
        }
    }
    __syncthreads();
    if (t == 0) {
        int need = k;
        int base = cntGT;
        int ec = eqcnt; if (ec > 1024) ec = 1024;
        if (ec > need) {
            for (int a = 1; a < ec; ++a) {
                int v = eqbuf[a]; int jj = a - 1;
                while (jj >= 0 && eqbuf[jj] > v) { eqbuf[jj + 1] = eqbuf[jj]; --jj; }
                eqbuf[jj + 1] = v;
            }
        }
        for (int e = 0; e < need && e < ec && base + e < NPTS; ++e)
            g_idx[b * NPTS + base + e] = eqbuf[e];
    }
}

// ================= kernel 3: double-buffered cp.async plane pooling =================
// One block per (b,c); both planes issued via cp.async up front (128KB in flight);
// pool xm overlaps xa load. 16 warps, warp-per-patch, pitch 136 (cp.async aligned,
// near-conflict-free lane->bank map since all lanes share one patch).
#define K3P 136
#define K3PLANE (128 * K3P)

__device__ __forceinline__ void k3_issue(float* buf, const float* __restrict__ gsrc, int t) {
    #pragma unroll
    for (int i = 0; i < 8; ++i) {
        int idx = t + i * 512;              // 4096 chunks of 16B
        int row = idx >> 5, col = idx & 31;
        uint32_t daddr;
        asm("{ .reg .u64 tmp; cvta.to.shared.u64 tmp, %1; cvt.u32.u64 %0, tmp; }"
            : "=r"(daddr) : "l"(buf + row * K3P + col * 4));
        asm volatile("cp.async.cg.shared.global [%0], [%1], 16;"
                     :: "r"(daddr), "l"(gsrc + row * WW + col * 4));
    }
    asm volatile("cp.async.commit_group;");
}

__global__ void __launch_bounds__(512) k3_pool(const float* __restrict__ xm,
                                               const float* __restrict__ xa) {
    extern __shared__ float sp[];            // [2][K3PLANE], then int s_hw[512]
    int* s_hw = (int*)(sp + 2 * K3PLANE);
    int c = blockIdx.x, b = blockIdx.y;
    int t = threadIdx.x, lane = t & 31, w = t >> 5;

    const float* pm = xm + (size_t)(b * CH + c) * HWSZ;
    const float* pa = xa + (size_t)(b * CH + c) * HWSZ;
    k3_issue(sp, pm, t);                     // group 0
    k3_issue(sp + K3PLANE, pa, t);           // group 1

    for (int i = t; i < NPTS; i += 512) s_hw[i] = g_idx[b * NPTS + i];

    // per-lane sample decomposition: s1 = lane (0..31), s2 = lane+32 (valid < 49)
    int dy1 = lane / 7, dx1 = lane - dy1 * 7;
    bool has2 = (lane < 17);
    int s2 = lane + 32;
    int dy2 = s2 / 7, dx2 = s2 - dy2 * 7;

    asm volatile("cp.async.wait_group 1;");  // xm plane landed
    __syncthreads();

    #pragma unroll
    for (int s = 0; s < 2; ++s) {
        const float* pl = sp + s * K3PLANE;
        for (int p = w; p < NPTS; p += 16) {
            int hw = s_hw[p];
            int iy = hw >> 7, ix = hw & 127;
            float v1, v2s, v2m;
            if (iy >= 3 && iy <= 124 && ix >= 3 && ix <= 124) {
                const float* bse = pl + (iy - 3) * K3P + (ix - 3);
                v1 = bse[dy1 * K3P + dx1];
                float v2 = has2 ? bse[dy2 * K3P + dx2] : 0.f;
                v2s = has2 ? v2 : 0.f;
                v2m = has2 ? v2 : -CUDART_INF_F;
            } else {
                int y1 = iy + dy1 - 3, x1 = ix + dx1 - 3;
                float w1 = 1.f;
                if (y1 < 0) { y1 = 0; w1 = 0.5f; } else if (y1 > 127) { y1 = 127; w1 = 0.5f; }
                if (x1 < 0) { x1 = 0; w1 *= 0.5f; } else if (x1 > 127) { x1 = 127; w1 *= 0.5f; }
                v1 = pl[y1 * K3P + x1] * w1;
                if (has2) {
                    int y2 = iy + dy2 - 3, x2 = ix + dx2 - 3;
                    float w2 = 1.f;
                    if (y2 < 0) { y2 = 0; w2 = 0.5f; } else if (y2 > 127) { y2 = 127; w2 = 0.5f; }
                    if (x2 < 0) { x2 = 0; w2 *= 0.5f; } else if (x2 > 127) { x2 = 127; w2 *= 0.5f; }
                    float v2 = pl[y2 * K3P + x2] * w2;
                    v2s = v2; v2m = v2;
                } else { v2s = 0.f; v2m = -CUDART_INF_F; }
            }
            float sum = v1 + v2s;
            float mx  = fmaxf(v1, v2m);
            #pragma unroll
            for (int o = 16; o; o >>= 1) {
                sum += __shfl_xor_sync(0xffffffffu, sum, o);
                mx = fmaxf(mx, __shfl_xor_sync(0xffffffffu, mx, o));
            }
            if (lane == 0) {
                float r = 0.5f * (sum * (1.f / 49.f) + mx);
                if (s == 0) {
                    g_vmt[(b * CH + c) * NPAD + p] = r;
                } else {
                    g_vat[(b * CH + c) * NPAD + p] = r;
                    g_vaux[(b * NPTS + p) * CH + c] = r;
                }
            }
        }
        if (s == 0) {
            asm volatile("cp.async.wait_group 0;");  // xa plane landed
            __syncthreads();
        }
    }
}

// ================= kernel 4: 512-thread split-m attention + MLP + proj + scatter =================
#define SM_QS 0
#define SM_T  9216
#define SM_S  27648
#define SM_VH 46080
#define SM_TOT 54400

__global__ void __launch_bounds__(512, 1)
k4_attn(const float* __restrict__ fc1w, const float* __restrict__ fc1b,
        const float* __restrict__ fc2w, const float* __restrict__ fc2b,
        const float* __restrict__ pw,   const float* __restrict__ pb,
        float* __restrict__ out) {
    extern __shared__ float sm[];
    float* Qs  = sm + SM_QS;
    float* Tk  = sm + SM_T;
    float* S_t = sm + SM_S;
    float* Vh  = sm + SM_VH;

    const int t   = threadIdx.x;
    const int tx  = t & 31, ty = t >> 5;
    const int g   = ty >> 3, tyg = ty & 7;
    const int b   = blockIdx.y;
    const int r0  = blockIdx.x * 32;
    const int nrows = min(32, NPTS - r0);

    for (int idx4 = t; idx4 < 2048; idx4 += 512) {
        int k = idx4 >> 3, i4 = (idx4 & 7) * 4;
        float4 v = *reinterpret_cast<const float4*>(&g_vmt[(b * CH + k) * NPAD + r0 + i4]);
        *reinterpret_cast<float4*>(&Qs[k * 36 + i4]) = v;
    }
    __syncthreads();

    for (int mt = 0; mt < 8; ++mt) {
        for (int idx4 = t; idx4 < 4096; idx4 += 512) {
            int tile = idx4 >> 11;
            int k = (idx4 >> 3) & 255, i4 = (idx4 & 7) * 4;
            int m0 = (8 * tile + mt) * 32;
            float4 v = *reinterpret_cast<const float4*>(&g_vat[(b * CH + k) * NPAD + m0 + i4]);
            *reinterpret_cast<float4*>(&Tk[tile * 9216 + k * 36 + i4]) = v;
        }
        __syncthreads();
        int m0g = (8 * g + mt) * 32;
        const float* Tg = Tk + g * 9216;
        u64 s01 = pk2(0.f, 0.f), s23 = pk2(0.f, 0.f);
        #pragma unroll 8
        for (int k = 0; k < 256; ++k) {
            ulonglong2 q = *reinterpret_cast<const ulonglong2*>(&Qs[k * 36 + 4 * tyg]);
            float kk = Tg[k * 36 + tx];
            u64 kk2 = pk2(kk, kk);
            s01 = f2fma(q.x, kk2, s01);
            s23 = f2fma(q.y, kk2, s23);
        }
        float a0, a1, a2, a3;
        upk2(a0, a1, s01); upk2(a2, a3, s23);
        *reinterpret_cast<float4*>(&S_t[(m0g + tx) * 36 + 4 * tyg]) =
            make_float4(a0 * 0.0625f, a1 * 0.0625f, a2 * 0.0625f, a3 * 0.0625f);
        __syncthreads();
    }

    #pragma unroll
    for (int i = 0; i < 2; ++i) {
        int r = 2 * ty + i;
        float mx = -CUDART_INF_F;
        for (int m = tx; m < NPTS; m += 32) mx = fmaxf(mx, S_t[m * 36 + r]);
        #pragma unroll
        for (int o = 16; o; o >>= 1) mx = fmaxf(mx, __shfl_xor_sync(0xffffffffu, mx, o));
        float sum = 0.f;
        for (int m = tx; m < NPTS; m += 32) {
            float e = __expf(S_t[m * 36 + r] - mx);
            S_t[m * 36 + r] = e;
            sum += e;
        }
        #pragma unroll
        for (int o = 16; o; o >>= 1) sum += __shfl_xor_sync(0xffffffffu, sum, o);
        float inv = 1.f / sum;
        for (int m = tx; m < NPTS; m += 32) S_t[m * 36 + r] *= inv;
    }
    __syncthreads();

    u64 acc[4][4];
    #pragma unroll
    for (int i = 0; i < 4; ++i)
        #pragma unroll
        for (int j = 0; j < 4; ++j) acc[i][j] = pk2(0.f, 0.f);

    for (int mt = 0; mt < 8; ++mt) {
        for (int idx4 = t; idx4 < 4096; idx4 += 512) {
            int tile = idx4 >> 11;
            int m = (idx4 >> 6) & 31, c4 = (idx4 & 63) * 4;
            int m0 = (8 * tile + mt) * 32;
            float4 v = make_float4(0.f, 0.f, 0.f, 0.f);
            if (m0 + m < NPTS)
                v = *reinterpret_cast<const float4*>(&g_vaux[(b * NPTS + m0 + m) * CH + c4]);
            *reinterpret_cast<float4*>(&Tk[tile * 8320 + m * 260 + c4]) = v;
        }
        __syncthreads();
        int m0g = (8 * g + mt) * 32;
        int mlim = min(32, NPTS - m0g);
        const float* Vg = Tk + g * 8320;
        for (int m = 0; m < mlim; ++m) {
            ulonglong2 pp = *reinterpret_cast<const ulonglong2*>(&S_t[(m0g + m) * 36 + 4 * tyg]);
            float p0, p1, p2, p3;
            upk2(p0, p1, pp.x); upk2(p2, p3, pp.y);
            u64 a0 = pk2(p0, p0), a1 = pk2(p1, p1), a2 = pk2(p2, p2), a3 = pk2(p3, p3);
            #pragma unroll
            for (int j = 0; j < 4; ++j) {
                u64 v = *reinterpret_cast<const u64*>(&Vg[m * 260 + 64 * j + 2 * tx]);
                acc[0][j] = f2fma(a0, v, acc[0][j]);
                acc[1][j] = f2fma(a1, v, acc[1][j]);
                acc[2][j] = f2fma(a2, v, acc[2][j]);
                acc[3][j] = f2fma(a3, v, acc[3][j]);
            }
        }
        __syncthreads();
    }
    if (g == 0) {
        #pragma unroll
        for (int i = 0; i < 4; ++i)
            #pragma unroll
            for (int j = 0; j < 4; ++j)
                *reinterpret_cast<u64*>(&Vh[(4 * tyg + i) * 260 + 64 * j + 2 * tx]) = acc[i][j];
    }
    __syncthreads();
    if (g == 1) {
        #pragma unroll
        for (int i = 0; i < 4; ++i)
            #pragma unroll
            for (int j = 0; j < 4; ++j) {
                u64* p = reinterpret_cast<u64*>(&Vh[(4 * tyg + i) * 260 + 64 * j + 2 * tx]);
                *p = f2add(*p, acc[i][j]);
            }
    }
    __syncthreads();

    float* W1p  = Tk;
    float* Vf_t = S_t;
    float* W2s  = S_t + 9216;
    for (int idx = t; idx < 256 * 16; idx += 512) {
        int k = idx >> 4, j = idx & 15;
        float wa = fc1w[idx];
        float wb = fc1w[4096 + idx];
        float wc = fc1w[8192 + idx];
        W1p[k * 32 + 2 * j]     = wa + wc;
        W1p[k * 32 + 2 * j + 1] = wb - wc;
    }
    for (int idx = t; idx < 4096; idx += 512) W2s[idx] = fc2w[idx];
    __syncthreads();

    int jl = tx & 15, half = tx >> 4;
    float hreg[2];
    #pragma unroll
    for (int i = 0; i < 2; ++i) {
        int r = 2 * ty + i;
        u64 hp = pk2(0.f, 0.f);
        int k0 = half * 128;
        #pragma unroll 4
        for (int k = k0; k < k0 + 128; ++k) {
            float vm = Qs[k * 36 + r];
            float vh = Vh[r * 260 + k];
            u64 w = *reinterpret_cast<const u64*>(&W1p[k * 32 + 2 * jl]);
            hp = f2fma(pk2(vm, vh), w, hp);
        }
        float hx, hy; upk2(hx, hy, hp);
        float h = hx + hy;
        h += __shfl_xor_sync(0xffffffffu, h, 16);
        h += fc1b[jl];
        hreg[i] = fmaxf(h, 0.f);
    }

    #pragma unroll
    for (int i = 0; i < 2; ++i) {
        int r = 2 * ty + i;
        for (int cb = 0; cb < 256; cb += 32) {
            int c = cb + tx;
            float gg = fc2b[c];
            #pragma unroll
            for (int jj = 0; jj < 16; ++jj) {
                float hj = __shfl_sync(0xffffffffu, hreg[i], jj);
                gg += hj * W2s[jj * 256 + c];
            }
            gg = 1.f / (1.f + __expf(-gg));
            float vm = Qs[c * 36 + r];
            float vh = Vh[r * 260 + c];
            Vf_t[c * 36 + r] = vm + gg * (vm - vh);
        }
    }
    __syncthreads();

    u64 pacc[4][4];
    #pragma unroll
    for (int i = 0; i < 4; ++i)
        #pragma unroll
        for (int j = 0; j < 4; ++j) pacc[i][j] = pk2(0.f, 0.f);

    for (int kt = 0; kt < 4; ++kt) {
        for (int idx4 = t; idx4 < 4096; idx4 += 512) {
            int tile = idx4 >> 11;
            int kk = (idx4 >> 6) & 31, c4 = (idx4 & 63) * 4;
            int k0 = (4 * tile + kt) * 32;
            float4 v = *reinterpret_cast<const float4*>(&pw[(k0 + kk) * 256 + c4]);
            *reinterpret_cast<float4*>(&Tk[tile * 8320 + kk * 260 + c4]) = v;
        }
        __syncthreads();
        int k0g = (4 * g + kt) * 32;
        const float* Pg = Tk + g * 8320;
        for (int kk = 0; kk < 32; ++kk) {
            ulonglong2 ff = *reinterpret_cast<const ulonglong2*>(&Vf_t[(k0g + kk) * 36 + 4 * tyg]);
            float f0, f1, f2, f3;
            upk2(f0, f1, ff.x); upk2(f2, f3, ff.y);
            u64 a0 = pk2(f0, f0), a1 = pk2(f1, f1), a2 = pk2(f2, f2), a3 = pk2(f3, f3);
            #pragma unroll
            for (int j = 0; j < 4; ++j) {
                u64 w = *reinterpret_cast<const u64*>(&Pg[kk * 260 + 64 * j + 2 * tx]);
                pacc[0][j] = f2fma(a0, w, pacc[0][j]);
                pacc[1][j] = f2fma(a1, w, pacc[1][j]);
                pacc[2][j] = f2fma(a2, w, pacc[2][j]);
                pacc[3][j] = f2fma(a3, w, pacc[3][j]);
            }
        }
        __syncthreads();
    }
    if (g == 0) {
        #pragma unroll
        for (int i = 0; i < 4; ++i)
            #pragma unroll
            for (int j = 0; j < 4; ++j)
                *reinterpret_cast<u64*>(&Vh[(4 * tyg + i) * 260 + 64 * j + 2 * tx]) = pacc[i][j];
    }
    __syncthreads();
    if (g == 1) {
        #pragma unroll
        for (int i = 0; i < 4; ++i) {
            int r = 4 * tyg + i;
            if (r < nrows) {
                int hw = g_idx[b * NPTS + r0 + r];
                float* ob = out + (size_t)b * CH * HWSZ + hw;
                #pragma unroll
                for (int j = 0; j < 4; ++j) {
                    int c = 64 * j + 2 * tx;
                    u64 prev = *reinterpret_cast<const u64*>(&Vh[r * 260 + c]);
                    float v0, v1; upk2(v0, v1, f2add(prev, pacc[i][j]));
                    ob[(size_t)c * HWSZ]       += v0 + pb[c];
                    ob[(size_t)(c + 1) * HWSZ] += v1 + pb[c + 1];
                }
            }
        }
    }
}

// ================= launch =================
extern "C" void kernel_launch(void* const* d_in, const int* in_sizes, int n_in,
                              void* d_out, int out_size) {
    const float* xm   = (const float*)d_in[0];
    const float* xa   = (const float*)d_in[1];
    const float* sw   = (const float*)d_in[2];
    const float* fc1w = (const float*)d_in[4];
    const float* fc1b = (const float*)d_in[5];
    const float* fc2w = (const float*)d_in[6];
    const float* fc2b = (const float*)d_in[7];
    const float* pw   = (const float*)d_in[8];
    const float* pb   = (const float*)d_in[9];
    float* out = (float*)d_out;

    const int K3_SMEM = 2 * K3PLANE * 4 + NPAD * 4;  // 141312 B
    const int K4_SMEM = SM_TOT * 4;                  // 217600 B
    cudaFuncSetAttribute(k3_pool, cudaFuncAttributeMaxDynamicSharedMemorySize, K3_SMEM);
    cudaFuncSetAttribute(k4_attn, cudaFuncAttributeMaxDynamicSharedMemorySize, K4_SMEM);

    k1_copy_score<<<dim3(128, 8), 256>>>(xm, sw, out);
    k1b_reduce<<<128, 256>>>();
    k2_topk<<<BATCH, 512>>>();
    k3_pool<<<dim3(CH, BATCH), 512, K3_SMEM>>>(xm, xa);
    k4_attn<<<dim3(16, BATCH), 512, K4_SMEM>>>(fc1w, fc1b, fc2w, fc2b, pw, pb, out);
}

// round 7
// speedup vs baseline: 1.3220x; 1.3220x over previous
#include <cuda_runtime.h>
#include <math_constants.h>
#include <stdint.h>

#define BATCH 8
#define CH 256
#define HH 128
#define WW 128
#define HWSZ 16384
#define NPTS 500
#define NPAD 512
#define NHID 16

typedef unsigned long long u64;

// ---------------- scratch ----------------
__device__ float g_score[BATCH * HWSZ];
__device__ int   g_idx[BATCH * NPTS];
__device__ float g_vmt [BATCH * CH * NPAD];   // v_main transposed [b][c][n], zero-padded
__device__ float g_vat [BATCH * CH * NPAD];   // v_aux  transposed [b][c][n]
__device__ float g_vaux[BATCH * NPTS * CH];   // v_aux row-major [b][n][c]

// ---------------- f32x2 helpers ----------------
__device__ __forceinline__ u64 pk2(float x, float y) {
    u64 d; asm("mov.b64 %0, {%1, %2};" : "=l"(d) : "f"(x), "f"(y)); return d;
}
__device__ __forceinline__ void upk2(float& x, float& y, u64 d) {
    asm("mov.b64 {%0, %1}, %2;" : "=f"(x), "=f"(y) : "l"(d));
}
__device__ __forceinline__ u64 f2fma(u64 a, u64 b, u64 c) {
    u64 d; asm("fma.rn.f32x2 %0, %1, %2, %3;" : "=l"(d) : "l"(a), "l"(b), "l"(c)); return d;
}
__device__ __forceinline__ u64 f2add(u64 a, u64 b) {
    u64 d; asm("add.rn.f32x2 %0, %1, %2;" : "=l"(d) : "l"(a), "l"(b)); return d;
}

// ================= kernel 1: fused copy + scorer, in-block channel reduce =================
// 1024 blocks x 256 threads: warp w owns channels [32w,32w+32) of 32 pixel-quads.
// Deterministic smem reduce across the 8 warps -> g_score directly (no partial buffer).
__global__ void __launch_bounds__(256) k1_copy_score(const float* __restrict__ xm,
                                                     const float* __restrict__ sw,
                                                     float* __restrict__ out) {
    __shared__ float s_w[CH];
    __shared__ float4 part[8][32];
    int t = threadIdx.x, lane = t & 31, w = t >> 5;
    s_w[t] = sw[t];
    __syncthreads();

    int gp = (blockIdx.x * 32 + lane) * 4;    // pixel index
    int b  = gp >> 14;
    int hw = gp & (HWSZ - 1);
    const float4* src = reinterpret_cast<const float4*>(xm + (size_t)(b * CH + 32 * w) * HWSZ + hw);
    float4*       dst = reinterpret_cast<float4*>(out + (size_t)(b * CH + 32 * w) * HWSZ + hw);

    float a0 = 0.f, a1 = 0.f, a2 = 0.f, a3 = 0.f;
    #pragma unroll 8
    for (int i = 0; i < 32; ++i) {
        float4 v = src[i * (HWSZ / 4)];
        dst[i * (HWSZ / 4)] = v;
        float wt = s_w[32 * w + i];
        a0 += v.x * wt; a1 += v.y * wt; a2 += v.z * wt; a3 += v.w * wt;
    }
    part[w][lane] = make_float4(a0, a1, a2, a3);
    __syncthreads();
    if (w == 0) {
        float4 s = part[0][lane];
        #pragma unroll
        for (int r = 1; r < 8; ++r) {
            float4 v = part[r][lane];
            s.x += v.x; s.y += v.y; s.z += v.z; s.w += v.w;
        }
        *reinterpret_cast<float4*>(g_score + gp) = s;
    }
}

// ================= kernel 2: exact top-500 per batch via radix select =================
__global__ void k2_topk() {
    __shared__ unsigned hist[256];
    __shared__ unsigned sh_pref;
    __shared__ int sh_k;
    __shared__ int cntGT, eqcnt;
    __shared__ int eqbuf[1024];

    int b = blockIdx.x, t = threadIdx.x, bd = blockDim.x;
    const float* sc = g_score + b * HWSZ;

    unsigned prefix = 0;
    int k = NPTS;
    for (int byte = 3; byte >= 0; --byte) {
        if (t < 256) hist[t] = 0;
        __syncthreads();
        int shamt = byte * 8;
        for (int i = t; i < HWSZ; i += bd) {
            unsigned u = __float_as_uint(sc[i]);
            u = (u & 0x80000000u) ? ~u : (u | 0x80000000u);
            bool m = (byte == 3) || ((u >> (shamt + 8)) == prefix);
            if (m) atomicAdd(&hist[(u >> shamt) & 255u], 1u);
        }
        __syncthreads();
        if (t == 0) {
            int cum = 0, bin;
            for (bin = 255; bin >= 0; --bin) {
                int h = (int)hist[bin];
                if (cum + h >= k) break;
                cum += h;
            }
            if (bin < 0) bin = 0;
            sh_pref = (prefix << 8) | (unsigned)bin;
            sh_k = k - cum;
        }
        __syncthreads();
        prefix = sh_pref; k = sh_k;
        __syncthreads();
    }
    unsigned T = prefix;
    if (t == 0) { cntGT = 0; eqcnt = 0; }
    __syncthreads();
    for (int i = t; i < HWSZ; i += bd) {
        unsigned u = __float_as_uint(sc[i]);
        u = (u & 0x80000000u) ? ~u : (u | 0x80000000u);
        if (u > T) {
            int p = atomicAdd(&cntGT, 1);
            if (p < NPTS) g_idx[b * NPTS + p] = i;
        } else if (u == T) {
            int e = atomicAdd(&eqcnt, 1);
            if (e < 1024) eqbuf[e] = i;
        }
    }
    __syncthreads();
    if (t == 0) {
        int need = k;
        int base = cntGT;
        int ec = eqcnt; if (ec > 1024) ec = 1024;
        if (ec > need) {
            for (int a = 1; a < ec; ++a) {
                int v = eqbuf[a]; int jj = a - 1;
                while (jj >= 0 && eqbuf[jj] > v) { eqbuf[jj + 1] = eqbuf[jj]; --jj; }
                eqbuf[jj + 1] = v;
            }
        }
        for (int e = 0; e < need && e < ec && base + e < NPTS; ++e)
            g_idx[b * NPTS + base + e] = eqbuf[e];
    }
}

// ================= kernel 3 (round-3 structure, split by source plane) =================
// grid (256, 8, 2): block loads ONE 64KB channel plane coalesced into smem, then
// thread-per-patch pooling (exact-grid: interior weight 1, clamped axis weight 0.5).
__global__ void __launch_bounds__(256) k3_pool(const float* __restrict__ xm,
                                               const float* __restrict__ xa) {
    extern __shared__ float sp[];          // [HWSZ] plane, then int s_hw[NPTS]
    int* s_hw = (int*)(sp + HWSZ);
    int c = blockIdx.x, b = blockIdx.y, s = blockIdx.z, t = threadIdx.x;

    for (int i = t; i < NPTS; i += 256) s_hw[i] = g_idx[b * NPTS + i];

    const float* src = (s == 0 ? xm : xa) + (size_t)(b * CH + c) * HWSZ;
    for (int i = t; i < HWSZ / 4; i += 256)
        reinterpret_cast<float4*>(sp)[i] = reinterpret_cast<const float4*>(src)[i];
    __syncthreads();

    for (int p = t; p < NPTS; p += 256) {
        int hw = s_hw[p];
        int iy = hw >> 7, ix = hw & 127;
        float sum = 0.f, mx = -CUDART_INF_F;
        if (iy >= 3 && iy <= 124 && ix >= 3 && ix <= 124) {
            const float* base = sp + (iy - 3) * WW + (ix - 3);
            #pragma unroll
            for (int dy = 0; dy < 7; ++dy) {
                #pragma unroll
                for (int dx = 0; dx < 7; ++dx) {
                    float v = base[dy * WW + dx];
                    sum += v; mx = fmaxf(mx, v);
                }
            }
        } else {
            #pragma unroll
            for (int dy = -3; dy <= 3; ++dy) {
                int yy = iy + dy; float wy = 1.f;
                if (yy < 0) { yy = 0; wy = 0.5f; } else if (yy > 127) { yy = 127; wy = 0.5f; }
                #pragma unroll
                for (int dx = -3; dx <= 3; ++dx) {
                    int xx = ix + dx; float wx = wy;
                    if (xx < 0) { xx = 0; wx *= 0.5f; } else if (xx > 127) { xx = 127; wx *= 0.5f; }
                    float v = sp[yy * WW + xx] * wx;
                    sum += v; mx = fmaxf(mx, v);
                }
            }
        }
        float r = 0.5f * (sum * (1.f / 49.f) + mx);
        if (s == 0) {
            g_vmt[(b * CH + c) * NPAD + p] = r;
        } else {
            g_vat[(b * CH + c) * NPAD + p] = r;
            g_vaux[(b * NPTS + p) * CH + c] = r;
        }
    }
}

// ================= kernel 4: 512-thread split-m attention + MLP + proj + scatter =================
#define SM_QS 0
#define SM_T  9216
#define SM_S  27648
#define SM_VH 46080
#define SM_TOT 54400

__global__ void __launch_bounds__(512, 1)
k4_attn(const float* __restrict__ fc1w, const float* __restrict__ fc1b,
        const float* __restrict__ fc2w, const float* __restrict__ fc2b,
        const float* __restrict__ pw,   const float* __restrict__ pb,
        float* __restrict__ out) {
    extern __shared__ float sm[];
    float* Qs  = sm + SM_QS;
    float* Tk  = sm + SM_T;
    float* S_t = sm + SM_S;
    float* Vh  = sm + SM_VH;

    const int t   = threadIdx.x;
    const int tx  = t & 31, ty = t >> 5;
    const int g   = ty >> 3, tyg = ty & 7;
    const int b   = blockIdx.y;
    const int r0  = blockIdx.x * 32;
    const int nrows = min(32, NPTS - r0);

    for (int idx4 = t; idx4 < 2048; idx4 += 512) {
        int k = idx4 >> 3, i4 = (idx4 & 7) * 4;
        float4 v = *reinterpret_cast<const float4*>(&g_vmt[(b * CH + k) * NPAD + r0 + i4]);
        *reinterpret_cast<float4*>(&Qs[k * 36 + i4]) = v;
    }
    __syncthreads();

    for (int mt = 0; mt < 8; ++mt) {
        for (int idx4 = t; idx4 < 4096; idx4 += 512) {
            int tile = idx4 >> 11;
            int k = (idx4 >> 3) & 255, i4 = (idx4 & 7) * 4;
            int m0 = (8 * tile + mt) * 32;
            float4 v = *reinterpret_cast<const float4*>(&g_vat[(b * CH + k) * NPAD + m0 + i4]);
            *reinterpret_cast<float4*>(&Tk[tile * 9216 + k * 36 + i4]) = v;
        }
        __syncthreads();
        int m0g = (8 * g + mt) * 32;
        const float* Tg = Tk + g * 9216;
        u64 s01 = pk2(0.f, 0.f), s23 = pk2(0.f, 0.f);
        #pragma unroll 8
        for (int k = 0; k < 256; ++k) {
            ulonglong2 q = *reinterpret_cast<const ulonglong2*>(&Qs[k * 36 + 4 * tyg]);
            float kk = Tg[k * 36 + tx];
            u64 kk2 = pk2(kk, kk);
            s01 = f2fma(q.x, kk2, s01);
            s23 = f2fma(q.y, kk2, s23);
        }
        float a0, a1, a2, a3;
        upk2(a0, a1, s01); upk2(a2, a3, s23);
        *reinterpret_cast<float4*>(&S_t[(m0g + tx) * 36 + 4 * tyg]) =
            make_float4(a0 * 0.0625f, a1 * 0.0625f, a2 * 0.0625f, a3 * 0.0625f);
        __syncthreads();
    }

    #pragma unroll
    for (int i = 0; i < 2; ++i) {
        int r = 2 * ty + i;
        float mx = -CUDART_INF_F;
        for (int m = tx; m < NPTS; m += 32) mx = fmaxf(mx, S_t[m * 36 + r]);
        #pragma unroll
        for (int o = 16; o; o >>= 1) mx = fmaxf(mx, __shfl_xor_sync(0xffffffffu, mx, o));
        float sum = 0.f;
        for (int m = tx; m < NPTS; m += 32) {
            float e = __expf(S_t[m * 36 + r] - mx);
            S_t[m * 36 + r] = e;
            sum += e;
        }
        #pragma unroll
        for (int o = 16; o; o >>= 1) sum += __shfl_xor_sync(0xffffffffu, sum, o);
        float inv = 1.f / sum;
        for (int m = tx; m < NPTS; m += 32) S_t[m * 36 + r] *= inv;
    }
    __syncthreads();

    u64 acc[4][4];
    #pragma unroll
    for (int i = 0; i < 4; ++i)
        #pragma unroll
        for (int j = 0; j < 4; ++j) acc[i][j] = pk2(0.f, 0.f);

    for (int mt = 0; mt < 8; ++mt) {
        for (int idx4 = t; idx4 < 4096; idx4 += 512) {
            int tile = idx4 >> 11;
            int m = (idx4 >> 6) & 31, c4 = (idx4 & 63) * 4;
            int m0 = (8 * tile + mt) * 32;
            float4 v = make_float4(0.f, 0.f, 0.f, 0.f);
            if (m0 + m < NPTS)
                v = *reinterpret_cast<const float4*>(&g_vaux[(b * NPTS + m0 + m) * CH + c4]);
            *reinterpret_cast<float4*>(&Tk[tile * 8320 + m * 260 + c4]) = v;
        }
        __syncthreads();
        int m0g = (8 * g + mt) * 32;
        int mlim = min(32, NPTS - m0g);
        const float* Vg = Tk + g * 8320;
        for (int m = 0; m < mlim; ++m) {
            ulonglong2 pp = *reinterpret_cast<const ulonglong2*>(&S_t[(m0g + m) * 36 + 4 * tyg]);
            float p0, p1, p2, p3;
            upk2(p0, p1, pp.x); upk2(p2, p3, pp.y);
            u64 a0 = pk2(p0, p0), a1 = pk2(p1, p1), a2 = pk2(p2, p2), a3 = pk2(p3, p3);
            #pragma unroll
            for (int j = 0; j < 4; ++j) {
                u64 v = *reinterpret_cast<const u64*>(&Vg[m * 260 + 64 * j + 2 * tx]);
                acc[0][j] = f2fma(a0, v, acc[0][j]);
                acc[1][j] = f2fma(a1, v, acc[1][j]);
                acc[2][j] = f2fma(a2, v, acc[2][j]);
                acc[3][j] = f2fma(a3, v, acc[3][j]);
            }
        }
        __syncthreads();
    }
    if (g == 0) {
        #pragma unroll
        for (int i = 0; i < 4; ++i)
            #pragma unroll
            for (int j = 0; j < 4; ++j)
                *reinterpret_cast<u64*>(&Vh[(4 * tyg + i) * 260 + 64 * j + 2 * tx]) = acc[i][j];
    }
    __syncthreads();
    if (g == 1) {
        #pragma unroll
        for (int i = 0; i < 4; ++i)
            #pragma unroll
            for (int j = 0; j < 4; ++j) {
                u64* p = reinterpret_cast<u64*>(&Vh[(4 * tyg + i) * 260 + 64 * j + 2 * tx]);
                *p = f2add(*p, acc[i][j]);
            }
    }
    __syncthreads();

    float* W1p  = Tk;
    float* Vf_t = S_t;
    float* W2s  = S_t + 9216;
    for (int idx = t; idx < 256 * 16; idx += 512) {
        int k = idx >> 4, j = idx & 15;
        float wa = fc1w[idx];
        float wb = fc1w[4096 + idx];
        float wc = fc1w[8192 + idx];
        W1p[k * 32 + 2 * j]     = wa + wc;
        W1p[k * 32 + 2 * j + 1] = wb - wc;
    }
    for (int idx = t; idx < 4096; idx += 512) W2s[idx] = fc2w[idx];
    __syncthreads();

    int jl = tx & 15, half = tx >> 4;
    float hreg[2];
    #pragma unroll
    for (int i = 0; i < 2; ++i) {
        int r = 2 * ty + i;
        u64 hp = pk2(0.f, 0.f);
        int k0 = half * 128;
        #pragma unroll 4
        for (int k = k0; k < k0 + 128; ++k) {
            float vm = Qs[k * 36 + r];
            float vh = Vh[r * 260 + k];
            u64 w = *reinterpret_cast<const u64*>(&W1p[k * 32 + 2 * jl]);
            hp = f2fma(pk2(vm, vh), w, hp);
        }
        float hx, hy; upk2(hx, hy, hp);
        float h = hx + hy;
        h += __shfl_xor_sync(0xffffffffu, h, 16);
        h += fc1b[jl];
        hreg[i] = fmaxf(h, 0.f);
    }

    #pragma unroll
    for (int i = 0; i < 2; ++i) {
        int r = 2 * ty + i;
        for (int cb = 0; cb < 256; cb += 32) {
            int c = cb + tx;
            float gg = fc2b[c];
            #pragma unroll
            for (int jj = 0; jj < 16; ++jj) {
                float hj = __shfl_sync(0xffffffffu, hreg[i], jj);
                gg += hj * W2s[jj * 256 + c];
            }
            gg = 1.f / (1.f + __expf(-gg));
            float vm = Qs[c * 36 + r];
            float vh = Vh[r * 260 + c];
            Vf_t[c * 36 + r] = vm + gg * (vm - vh);
        }
    }
    __syncthreads();

    u64 pacc[4][4];
    #pragma unroll
    for (int i = 0; i < 4; ++i)
        #pragma unroll
        for (int j = 0; j < 4; ++j) pacc[i][j] = pk2(0.f, 0.f);

    for (int kt = 0; kt < 4; ++kt) {
        for (int idx4 = t; idx4 < 4096; idx4 += 512) {
            int tile = idx4 >> 11;
            int kk = (idx4 >> 6) & 31, c4 = (idx4 & 63) * 4;
            int k0 = (4 * tile + kt) * 32;
            float4 v = *reinterpret_cast<const float4*>(&pw[(k0 + kk) * 256 + c4]);
            *reinterpret_cast<float4*>(&Tk[tile * 8320 + kk * 260 + c4]) = v;
        }
        __syncthreads();
        int k0g = (4 * g + kt) * 32;
        const float* Pg = Tk + g * 8320;
        for (int kk = 0; kk < 32; ++kk) {
            ulonglong2 ff = *reinterpret_cast<const ulonglong2*>(&Vf_t[(k0g + kk) * 36 + 4 * tyg]);
            float f0, f1, f2, f3;
            upk2(f0, f1, ff.x); upk2(f2, f3, ff.y);
            u64 a0 = pk2(f0, f0), a1 = pk2(f1, f1), a2 = pk2(f2, f2), a3 = pk2(f3, f3);
            #pragma unroll
            for (int j = 0; j < 4; ++j) {
                u64 w = *reinterpret_cast<const u64*>(&Pg[kk * 260 + 64 * j + 2 * tx]);
                pacc[0][j] = f2fma(a0, w, pacc[0][j]);
                pacc[1][j] = f2fma(a1, w, pacc[1][j]);
                pacc[2][j] = f2fma(a2, w, pacc[2][j]);
                pacc[3][j] = f2fma(a3, w, pacc[3][j]);
            }
        }
        __syncthreads();
    }
    if (g == 0) {
        #pragma unroll
        for (int i = 0; i < 4; ++i)
            #pragma unroll
            for (int j = 0; j < 4; ++j)
                *reinterpret_cast<u64*>(&Vh[(4 * tyg + i) * 260 + 64 * j + 2 * tx]) = pacc[i][j];
    }
    __syncthreads();
    if (g == 1) {
        #pragma unroll
        for (int i = 0; i < 4; ++i) {
            int r = 4 * tyg + i;
            if (r < nrows) {
                int hw = g_idx[b * NPTS + r0 + r];
                float* ob = out + (size_t)b * CH * HWSZ + hw;
                #pragma unroll
                for (int j = 0; j < 4; ++j) {
                    int c = 64 * j + 2 * tx;
                    u64 prev = *reinterpret_cast<const u64*>(&Vh[r * 260 + c]);
                    float v0, v1; upk2(v0, v1, f2add(prev, pacc[i][j]));
                    ob[(size_t)c * HWSZ]       += v0 + pb[c];
                    ob[(size_t)(c + 1) * HWSZ] += v1 + pb[c + 1];
                }
            }
        }
    }
}

// ================= launch =================
extern "C" void kernel_launch(void* const* d_in, const int* in_sizes, int n_in,
                              void* d_out, int out_size) {
    const float* xm   = (const float*)d_in[0];
    const float* xa   = (const float*)d_in[1];
    const float* sw   = (const float*)d_in[2];
    const float* fc1w = (const float*)d_in[4];
    const float* fc1b = (const float*)d_in[5];
    const float* fc2w = (const float*)d_in[6];
    const float* fc2b = (const float*)d_in[7];
    const float* pw   = (const float*)d_in[8];
    const float* pb   = (const float*)d_in[9];
    float* out = (float*)d_out;

    const int K3_SMEM = HWSZ * 4 + NPAD * 4;   // 67584 B
    const int K4_SMEM = SM_TOT * 4;            // 217600 B
    cudaFuncSetAttribute(k3_pool, cudaFuncAttributeMaxDynamicSharedMemorySize, K3_SMEM);
    cudaFuncSetAttribute(k4_attn, cudaFuncAttributeMaxDynamicSharedMemorySize, K4_SMEM);

    k1_copy_score<<<1024, 256>>>(xm, sw, out);
    k2_topk<<<BATCH, 512>>>();
    k3_pool<<<dim3(CH, BATCH, 2), 256, K3_SMEM>>>(xm, xa);
    k4_attn<<<dim3(16, BATCH), 512, K4_SMEM>>>(fc1w, fc1b, fc2w, fc2b, pw, pb, out);
}

// round 8
// speedup vs baseline: 1.4501x; 1.0969x over previous
#include <cuda_runtime.h>
#include <math_constants.h>
#include <stdint.h>

#define BATCH 8
#define CH 256
#define HH 128
#define WW 128
#define HWSZ 16384
#define NPTS 500
#define NPAD 512
#define NHID 16

typedef unsigned long long u64;

// ---------------- scratch ----------------
__device__ float g_score [BATCH * HWSZ];
__device__ float g_spart2[BATCH * HWSZ];      // second channel-half partial
__device__ int   g_idx[BATCH * NPTS];
__device__ float g_vmt [BATCH * CH * NPAD];   // v_main transposed [b][c][n], zero-padded
__device__ float g_vat [BATCH * CH * NPAD];   // v_aux  transposed [b][c][n]
__device__ float g_vaux[BATCH * NPTS * CH];   // v_aux row-major [b][n][c]

// ---------------- f32x2 helpers ----------------
__device__ __forceinline__ u64 pk2(float x, float y) {
    u64 d; asm("mov.b64 %0, {%1, %2};" : "=l"(d) : "f"(x), "f"(y)); return d;
}
__device__ __forceinline__ void upk2(float& x, float& y, u64 d) {
    asm("mov.b64 {%0, %1}, %2;" : "=f"(x), "=f"(y) : "l"(d));
}
__device__ __forceinline__ u64 f2fma(u64 a, u64 b, u64 c) {
    u64 d; asm("fma.rn.f32x2 %0, %1, %2, %3;" : "=l"(d) : "l"(a), "l"(b), "l"(c)); return d;
}
__device__ __forceinline__ u64 f2add(u64 a, u64 b) {
    u64 d; asm("add.rn.f32x2 %0, %1, %2;" : "=l"(d) : "l"(a), "l"(b)); return d;
}

// ================= kernel 1: fused copy + scorer, register-only partials =================
// grid (512, 2): split s covers channels [128s, 128s+128). Thread owns ONE pixel,
// loops 128 channels scalar (warp = 128B coalesced), single register accumulator.
// No smem reduce, no partial planes: split 0 -> g_score, split 1 -> g_spart2;
// k2 adds the two on read (deterministic).
__global__ void __launch_bounds__(256) k1_copy_score(const float* __restrict__ xm,
                                                     const float* __restrict__ sw,
                                                     float* __restrict__ out) {
    __shared__ float s_w[128];
    int t = threadIdx.x, s = blockIdx.y;
    if (t < 128) s_w[t] = sw[s * 128 + t];
    __syncthreads();

    int p  = blockIdx.x * 256 + t;       // pixel index in [0, BATCH*HWSZ)
    int b  = p >> 14;
    int hw = p & (HWSZ - 1);
    const float* src = xm + (size_t)(b * CH + s * 128) * HWSZ + hw;
    float*       dst = out + (size_t)(b * CH + s * 128) * HWSZ + hw;

    float a = 0.f;
    #pragma unroll 8
    for (int c = 0; c < 128; ++c) {
        float v = src[(size_t)c * HWSZ];
        dst[(size_t)c * HWSZ] = v;
        a += v * s_w[c];
    }
    (s == 0 ? g_score : g_spart2)[p] = a;
}

// ================= kernel 2: exact top-500 per batch via radix select =================
// Reads score as g_score + g_spart2 (fixed order -> deterministic).
__global__ void k2_topk() {
    __shared__ unsigned hist[256];
    __shared__ unsigned sh_pref;
    __shared__ int sh_k;
    __shared__ int cntGT, eqcnt;
    __shared__ int eqbuf[1024];

    int b = blockIdx.x, t = threadIdx.x, bd = blockDim.x;
    const float* sc  = g_score  + b * HWSZ;
    const float* sc2 = g_spart2 + b * HWSZ;

    unsigned prefix = 0;
    int k = NPTS;
    for (int byte = 3; byte >= 0; --byte) {
        if (t < 256) hist[t] = 0;
        __syncthreads();
        int shamt = byte * 8;
        for (int i = t; i < HWSZ; i += bd) {
            unsigned u = __float_as_uint(sc[i] + sc2[i]);
            u = (u & 0x80000000u) ? ~u : (u | 0x80000000u);
            bool m = (byte == 3) || ((u >> (shamt + 8)) == prefix);
            if (m) atomicAdd(&hist[(u >> shamt) & 255u], 1u);
        }
        __syncthreads();
        if (t == 0) {
            int cum = 0, bin;
            for (bin = 255; bin >= 0; --bin) {
                int h = (int)hist[bin];
                if (cum + h >= k) break;
                cum += h;
            }
            if (bin < 0) bin = 0;
            sh_pref = (prefix << 8) | (unsigned)bin;
            sh_k = k - cum;
        }
        __syncthreads();
        prefix = sh_pref; k = sh_k;
        __syncthreads();
    }
    unsigned T = prefix;
    if (t == 0) { cntGT = 0; eqcnt = 0; }
    __syncthreads();
    for (int i = t; i < HWSZ; i += bd) {
        unsigned u = __float_as_uint(sc[i] + sc2[i]);
        u = (u & 0x80000000u) ? ~u : (u | 0x80000000u);
        if (u > T) {
            int p = atomicAdd(&cntGT, 1);
            if (p < NPTS) g_idx[b * NPTS + p] = i;
        } else if (u == T) {
            int e = atomicAdd(&eqcnt, 1);
            if (e < 1024) eqbuf[e] = i;
        }
    }
    __syncthreads();
    if (t == 0) {
        int need = k;
        int base = cntGT;
        int ec = eqcnt; if (ec > 1024) ec = 1024;
        if (ec > need) {
            for (int a = 1; a < ec; ++a) {
                int v = eqbuf[a]; int jj = a - 1;
                while (jj >= 0 && eqbuf[jj] > v) { eqbuf[jj + 1] = eqbuf[jj]; --jj; }
                eqbuf[jj + 1] = v;
            }
        }
        for (int e = 0; e < need && e < ec && base + e < NPTS; ++e)
            g_idx[b * NPTS + base + e] = eqbuf[e];
    }
}

// ================= kernel 3 (round-5 exact): stream plane -> pool from smem =================
__global__ void __launch_bounds__(256) k3_pool(const float* __restrict__ xm,
                                               const float* __restrict__ xa) {
    extern __shared__ float sp[];
    int* s_hw = (int*)(sp + HWSZ);
    int c = blockIdx.x, b = blockIdx.y, t = threadIdx.x;

    for (int i = t; i < NPTS; i += 256) s_hw[i] = g_idx[b * NPTS + i];

    #pragma unroll
    for (int s = 0; s < 2; ++s) {
        const float* src = (s == 0 ? xm : xa) + (size_t)(b * CH + c) * HWSZ;
        __syncthreads();
        for (int i = t; i < HWSZ / 4; i += 256)
            reinterpret_cast<float4*>(sp)[i] = reinterpret_cast<const float4*>(src)[i];
        __syncthreads();

        for (int p = t; p < NPTS; p += 256) {
            int hw = s_hw[p];
            int iy = hw >> 7, ix = hw & 127;
            float sum = 0.f, mx = -CUDART_INF_F;
            if (iy >= 3 && iy <= 124 && ix >= 3 && ix <= 124) {
                const float* base = sp + (iy - 3) * WW + (ix - 3);
                #pragma unroll
                for (int dy = 0; dy < 7; ++dy) {
                    #pragma unroll
                    for (int dx = 0; dx < 7; ++dx) {
                        float v = base[dy * WW + dx];
                        sum += v; mx = fmaxf(mx, v);
                    }
                }
            } else {
                #pragma unroll
                for (int dy = -3; dy <= 3; ++dy) {
                    int yy = iy + dy; float wy = 1.f;
                    if (yy < 0) { yy = 0; wy = 0.5f; } else if (yy > 127) { yy = 127; wy = 0.5f; }
                    #pragma unroll
                    for (int dx = -3; dx <= 3; ++dx) {
                        int xx = ix + dx; float wx = wy;
                        if (xx < 0) { xx = 0; wx *= 0.5f; } else if (xx > 127) { xx = 127; wx *= 0.5f; }
                        float v = sp[yy * WW + xx] * wx;
                        sum += v; mx = fmaxf(mx, v);
                    }
                }
            }
            float r = 0.5f * (sum * (1.f / 49.f) + mx);
            if (s == 0) {
                g_vmt[(b * CH + c) * NPAD + p] = r;
            } else {
                g_vat[(b * CH + c) * NPAD + p] = r;
                g_vaux[(b * NPTS + p) * CH + c] = r;
            }
        }
    }
}

// ================= kernel 4 (round-5 exact): 512-thread split-m attention =================
#define SM_QS 0
#define SM_T  9216
#define SM_S  27648
#define SM_VH 46080
#define SM_TOT 54400

__global__ void __launch_bounds__(512, 1)
k4_attn(const float* __restrict__ fc1w, const float* __restrict__ fc1b,
        const float* __restrict__ fc2w, const float* __restrict__ fc2b,
        const float* __restrict__ pw,   const float* __restrict__ pb,
        float* __restrict__ out) {
    extern __shared__ float sm[];
    float* Qs  = sm + SM_QS;
    float* Tk  = sm + SM_T;
    float* S_t = sm + SM_S;
    float* Vh  = sm + SM_VH;

    const int t   = threadIdx.x;
    const int tx  = t & 31, ty = t >> 5;
    const int g   = ty >> 3, tyg = ty & 7;
    const int b   = blockIdx.y;
    const int r0  = blockIdx.x * 32;
    const int nrows = min(32, NPTS - r0);

    for (int idx4 = t; idx4 < 2048; idx4 += 512) {
        int k = idx4 >> 3, i4 = (idx4 & 7) * 4;
        float4 v = *reinterpret_cast<const float4*>(&g_vmt[(b * CH + k) * NPAD + r0 + i4]);
        *reinterpret_cast<float4*>(&Qs[k * 36 + i4]) = v;
    }
    __syncthreads();

    for (int mt = 0; mt < 8; ++mt) {
        for (int idx4 = t; idx4 < 4096; idx4 += 512) {
            int tile = idx4 >> 11;
            int k = (idx4 >> 3) & 255, i4 = (idx4 & 7) * 4;
            int m0 = (8 * tile + mt) * 32;
            float4 v = *reinterpret_cast<const float4*>(&g_vat[(b * CH + k) * NPAD + m0 + i4]);
            *reinterpret_cast<float4*>(&Tk[tile * 9216 + k * 36 + i4]) = v;
        }
        __syncthreads();
        int m0g = (8 * g + mt) * 32;
        const float* Tg = Tk + g * 9216;
        u64 s01 = pk2(0.f, 0.f), s23 = pk2(0.f, 0.f);
        #pragma unroll 8
        for (int k = 0; k < 256; ++k) {
            ulonglong2 q = *reinterpret_cast<const ulonglong2*>(&Qs[k * 36 + 4 * tyg]);
            float kk = Tg[k * 36 + tx];
            u64 kk2 = pk2(kk, kk);
            s01 = f2fma(q.x, kk2, s01);
            s23 = f2fma(q.y, kk2, s23);
        }
        float a0, a1, a2, a3;
        upk2(a0, a1, s01); upk2(a2, a3, s23);
        *reinterpret_cast<float4*>(&S_t[(m0g + tx) * 36 + 4 * tyg]) =
            make_float4(a0 * 0.0625f, a1 * 0.0625f, a2 * 0.0625f, a3 * 0.0625f);
        __syncthreads();
    }

    #pragma unroll
    for (int i = 0; i < 2; ++i) {
        int r = 2 * ty + i;
        float mx = -CUDART_INF_F;
        for (int m = tx; m < NPTS; m += 32) mx = fmaxf(mx, S_t[m * 36 + r]);
        #pragma unroll
        for (int o = 16; o; o >>= 1) mx = fmaxf(mx, __shfl_xor_sync(0xffffffffu, mx, o));
        float sum = 0.f;
        for (int m = tx; m < NPTS; m += 32) {
            float e = __expf(S_t[m * 36 + r] - mx);
            S_t[m * 36 + r] = e;
            sum += e;
        }
        #pragma unroll
        for (int o = 16; o; o >>= 1) sum += __shfl_xor_sync(0xffffffffu, sum, o);
        float inv = 1.f / sum;
        for (int m = tx; m < NPTS; m += 32) S_t[m * 36 + r] *= inv;
    }
    __syncthreads();

    u64 acc[4][4];
    #pragma unroll
    for (int i = 0; i < 4; ++i)
        #pragma unroll
        for (int j = 0; j < 4; ++j) acc[i][j] = pk2(0.f, 0.f);

    for (int mt = 0; mt < 8; ++mt) {
        for (int idx4 = t; idx4 < 4096; idx4 += 512) {
            int tile = idx4 >> 11;
            int m = (idx4 >> 6) & 31, c4 = (idx4 & 63) * 4;
            int m0 = (8 * tile + mt) * 32;
            float4 v = make_float4(0.f, 0.f, 0.f, 0.f);
            if (m0 + m < NPTS)
                v = *reinterpret_cast<const float4*>(&g_vaux[(b * NPTS + m0 + m) * CH + c4]);
            *reinterpret_cast<float4*>(&Tk[tile * 8320 + m * 260 + c4]) = v;
        }
        __syncthreads();
        int m0g = (8 * g + mt) * 32;
        int mlim = min(32, NPTS - m0g);
        const float* Vg = Tk + g * 8320;
        for (int m = 0; m < mlim; ++m) {
            ulonglong2 pp = *reinterpret_cast<const ulonglong2*>(&S_t[(m0g + m) * 36 + 4 * tyg]);
            float p0, p1, p2, p3;
            upk2(p0, p1, pp.x); upk2(p2, p3, pp.y);
            u64 a0 = pk2(p0, p0), a1 = pk2(p1, p1), a2 = pk2(p2, p2), a3 = pk2(p3, p3);
            #pragma unroll
            for (int j = 0; j < 4; ++j) {
                u64 v = *reinterpret_cast<const u64*>(&Vg[m * 260 + 64 * j + 2 * tx]);
                acc[0][j] = f2fma(a0, v, acc[0][j]);
                acc[1][j] = f2fma(a1, v, acc[1][j]);
                acc[2][j] = f2fma(a2, v, acc[2][j]);
                acc[3][j] = f2fma(a3, v, acc[3][j]);
            }
        }
        __syncthreads();
    }
    if (g == 0) {
        #pragma unroll
        for (int i = 0; i < 4; ++i)
            #pragma unroll
            for (int j = 0; j < 4; ++j)
                *reinterpret_cast<u64*>(&Vh[(4 * tyg + i) * 260 + 64 * j + 2 * tx]) = acc[i][j];
    }
    __syncthreads();
    if (g == 1) {
        #pragma unroll
        for (int i = 0; i < 4; ++i)
            #pragma unroll
            for (int j = 0; j < 4; ++j) {
                u64* p = reinterpret_cast<u64*>(&Vh[(4 * tyg + i) * 260 + 64 * j + 2 * tx]);
                *p = f2add(*p, acc[i][j]);
            }
    }
    __syncthreads();

    float* W1p  = Tk;
    float* Vf_t = S_t;
    float* W2s  = S_t + 9216;
    for (int idx = t; idx < 256 * 16; idx += 512) {
        int k = idx >> 4, j = idx & 15;
        float wa = fc1w[idx];
        float wb = fc1w[4096 + idx];
        float wc = fc1w[8192 + idx];
        W1p[k * 32 + 2 * j]     = wa + wc;
        W1p[k * 32 + 2 * j + 1] = wb - wc;
    }
    for (int idx = t; idx < 4096; idx += 512) W2s[idx] = fc2w[idx];
    __syncthreads();

    int jl = tx & 15, half = tx >> 4;
    float hreg[2];
    #pragma unroll
    for (int i = 0; i < 2; ++i) {
        int r = 2 * ty + i;
        u64 hp = pk2(0.f, 0.f);
        int k0 = half * 128;
        #pragma unroll 4
        for (int k = k0; k < k0 + 128; ++k) {
            float vm = Qs[k * 36 + r];
            float vh = Vh[r * 260 + k];
            u64 w = *reinterpret_cast<const u64*>(&W1p[k * 32 + 2 * jl]);
            hp = f2fma(pk2(vm, vh), w, hp);
        }
        float hx, hy; upk2(hx, hy, hp);
        float h = hx + hy;
        h += __shfl_xor_sync(0xffffffffu, h, 16);
        h += fc1b[jl];
        hreg[i] = fmaxf(h, 0.f);
    }

    #pragma unroll
    for (int i = 0; i < 2; ++i) {
        int r = 2 * ty + i;
        for (int cb = 0; cb < 256; cb += 32) {
            int c = cb + tx;
            float gg = fc2b[c];
            #pragma unroll
            for (int jj = 0; jj < 16; ++jj) {
                float hj = __shfl_sync(0xffffffffu, hreg[i], jj);
                gg += hj * W2s[jj * 256 + c];
            }
            gg = 1.f / (1.f + __expf(-gg));
            float vm = Qs[c * 36 + r];
            float vh = Vh[r * 260 + c];
            Vf_t[c * 36 + r] = vm + gg * (vm - vh);
        }
    }
    __syncthreads();

    u64 pacc[4][4];
    #pragma unroll
    for (int i = 0; i < 4; ++i)
        #pragma unroll
        for (int j = 0; j < 4; ++j) pacc[i][j] = pk2(0.f, 0.f);

    for (int kt = 0; kt < 4; ++kt) {
        for (int idx4 = t; idx4 < 4096; idx4 += 512) {
            int tile = idx4 >> 11;
            int kk = (idx4 >> 6) & 31, c4 = (idx4 & 63) * 4;
            int k0 = (4 * tile + kt) * 32;
            float4 v = *reinterpret_cast<const float4*>(&pw[(k0 + kk) * 256 + c4]);
            *reinterpret_cast<float4*>(&Tk[tile * 8320 + kk * 260 + c4]) = v;
        }
        __syncthreads();
        int k0g = (4 * g + kt) * 32;
        const float* Pg = Tk + g * 8320;
        for (int kk = 0; kk < 32; ++kk) {
            ulonglong2 ff = *reinterpret_cast<const ulonglong2*>(&Vf_t[(k0g + kk) * 36 + 4 * tyg]);
            float f0, f1, f2, f3;
            upk2(f0, f1, ff.x); upk2(f2, f3, ff.y);
            u64 a0 = pk2(f0, f0), a1 = pk2(f1, f1), a2 = pk2(f2, f2), a3 = pk2(f3, f3);
            #pragma unroll
            for (int j = 0; j < 4; ++j) {
                u64 w = *reinterpret_cast<const u64*>(&Pg[kk * 260 + 64 * j + 2 * tx]);
                pacc[0][j] = f2fma(a0, w, pacc[0][j]);
                pacc[1][j] = f2fma(a1, w, pacc[1][j]);
                pacc[2][j] = f2fma(a2, w, pacc[2][j]);
                pacc[3][j] = f2fma(a3, w, pacc[3][j]);
            }
        }
        __syncthreads();
    }
    if (g == 0) {
        #pragma unroll
        for (int i = 0; i < 4; ++i)
            #pragma unroll
            for (int j = 0; j < 4; ++j)
                *reinterpret_cast<u64*>(&Vh[(4 * tyg + i) * 260 + 64 * j + 2 * tx]) = pacc[i][j];
    }
    __syncthreads();
    if (g == 1) {
        #pragma unroll
        for (int i = 0; i < 4; ++i) {
            int r = 4 * tyg + i;
            if (r < nrows) {
                int hw = g_idx[b * NPTS + r0 + r];
                float* ob = out + (size_t)b * CH * HWSZ + hw;
                #pragma unroll
                for (int j = 0; j < 4; ++j) {
                    int c = 64 * j + 2 * tx;
                    u64 prev = *reinterpret_cast<const u64*>(&Vh[r * 260 + c]);
                    float v0, v1; upk2(v0, v1, f2add(prev, pacc[i][j]));
                    ob[(size_t)c * HWSZ]       += v0 + pb[c];
                    ob[(size_t)(c + 1) * HWSZ] += v1 + pb[c + 1];
                }
            }
        }
    }
}

// ================= launch =================
extern "C" void kernel_launch(void* const* d_in, const int* in_sizes, int n_in,
                              void* d_out, int out_size) {
    const float* xm   = (const float*)d_in[0];
    const float* xa   = (const float*)d_in[1];
    const float* sw   = (const float*)d_in[2];
    const float* fc1w = (const float*)d_in[4];
    const float* fc1b = (const float*)d_in[5];
    const float* fc2w = (const float*)d_in[6];
    const float* fc2b = (const float*)d_in[7];
    const float* pw   = (const float*)d_in[8];
    const float* pb   = (const float*)d_in[9];
    float* out = (float*)d_out;

    const int K3_SMEM = HWSZ * 4 + NPTS * 4;   // 67536 B
    const int K4_SMEM = SM_TOT * 4;            // 217600 B
    cudaFuncSetAttribute(k3_pool, cudaFuncAttributeMaxDynamicSharedMemorySize, K3_SMEM);
    cudaFuncSetAttribute(k4_attn, cudaFuncAttributeMaxDynamicSharedMemorySize, K4_SMEM);

    k1_copy_score<<<dim3(512, 2), 256>>>(xm, sw, out);
    k2_topk<<<BATCH, 512>>>();
    k3_pool<<<dim3(CH, BATCH), 256, K3_SMEM>>>(xm, xa);
    k4_attn<<<dim3(16, BATCH), 512, K4_SMEM>>>(fc1w, fc1b, fc2w, fc2b, pw, pb, out);
}

// round 9
// speedup vs baseline: 1.8588x; 1.2818x over previous
#include <cuda_runtime.h>
#include <math_constants.h>
#include <stdint.h>

#define BATCH 8
#define CH 256
#define HH 128
#define WW 128
#define HWSZ 16384
#define NPTS 500
#define NPAD 512
#define NHID 16

typedef unsigned long long u64;

// ---------------- scratch ----------------
__device__ float g_score [BATCH * HWSZ];
__device__ float g_spart2[BATCH * HWSZ];
__device__ int   g_idx[BATCH * NPTS];
__device__ float g_vmt [BATCH * CH * NPAD];   // v_main transposed [b][c][n], zero-padded
__device__ float g_vat [BATCH * CH * NPAD];   // v_aux  transposed [b][c][n], zero-padded
__device__ float g_vaux[BATCH * NPAD * CH];   // v_aux row-major [b][n][c], rows >=500 zero

// ---------------- f32x2 helpers (fc1 path) ----------------
__device__ __forceinline__ u64 pk2(float x, float y) {
    u64 d; asm("mov.b64 %0, {%1, %2};" : "=l"(d) : "f"(x), "f"(y)); return d;
}
__device__ __forceinline__ void upk2(float& x, float& y, u64 d) {
    asm("mov.b64 {%0, %1}, %2;" : "=f"(x), "=f"(y) : "l"(d));
}
__device__ __forceinline__ u64 f2fma(u64 a, u64 b, u64 c) {
    u64 d; asm("fma.rn.f32x2 %0, %1, %2, %3;" : "=l"(d) : "l"(a), "l"(b), "l"(c)); return d;
}

// ---------------- tensor-core + cp.async helpers ----------------
__device__ __forceinline__ void mma8(float* d, const uint32_t* a, const uint32_t* b) {
    asm volatile(
        "mma.sync.aligned.m16n8k8.row.col.f32.tf32.tf32.f32 "
        "{%0,%1,%2,%3},{%4,%5,%6,%7},{%8,%9},{%0,%1,%2,%3};"
        : "+f"(d[0]), "+f"(d[1]), "+f"(d[2]), "+f"(d[3])
        : "r"(a[0]), "r"(a[1]), "r"(a[2]), "r"(a[3]), "r"(b[0]), "r"(b[1]));
}
__device__ __forceinline__ void cp16(const void* smem_dst, const float* gsrc) {
    uint32_t d;
    asm("{ .reg .u64 tt; cvta.to.shared.u64 tt, %1; cvt.u32.u64 %0, tt; }" : "=r"(d) : "l"(smem_dst));
    asm volatile("cp.async.cg.shared.global [%0], [%1], 16;" :: "r"(d), "l"(gsrc));
}
#define CP_COMMIT() asm volatile("cp.async.commit_group;")
#define CP_WAIT1()  asm volatile("cp.async.wait_group 1;")
#define CP_WAIT0()  asm volatile("cp.async.wait_group 0;")

// ================= kernel 1: fused copy + scorer, register-only partials =================
__global__ void __launch_bounds__(256) k1_copy_score(const float* __restrict__ xm,
                                                     const float* __restrict__ sw,
                                                     float* __restrict__ out) {
    __shared__ float s_w[128];
    int t = threadIdx.x, s = blockIdx.y;
    if (t < 128) s_w[t] = sw[s * 128 + t];
    __syncthreads();

    int p  = blockIdx.x * 256 + t;
    int b  = p >> 14;
    int hw = p & (HWSZ - 1);
    const float* src = xm + (size_t)(b * CH + s * 128) * HWSZ + hw;
    float*       dst = out + (size_t)(b * CH + s * 128) * HWSZ + hw;

    float a = 0.f;
    #pragma unroll 8
    for (int c = 0; c < 128; ++c) {
        float v = src[(size_t)c * HWSZ];
        dst[(size_t)c * HWSZ] = v;
        a += v * s_w[c];
    }
    (s == 0 ? g_score : g_spart2)[p] = a;
}

// ================= kernel 2: exact top-500 per batch via radix select =================
__global__ void k2_topk() {
    __shared__ unsigned hist[256];
    __shared__ unsigned sh_pref;
    __shared__ int sh_k;
    __shared__ int cntGT, eqcnt;
    __shared__ int eqbuf[1024];

    int b = blockIdx.x, t = threadIdx.x, bd = blockDim.x;
    const float* sc  = g_score  + b * HWSZ;
    const float* sc2 = g_spart2 + b * HWSZ;

    unsigned prefix = 0;
    int k = NPTS;
    for (int byte = 3; byte >= 0; --byte) {
        if (t < 256) hist[t] = 0;
        __syncthreads();
        int shamt = byte * 8;
        for (int i = t; i < HWSZ; i += bd) {
            unsigned u = __float_as_uint(sc[i] + sc2[i]);
            u = (u & 0x80000000u) ? ~u : (u | 0x80000000u);
            bool m = (byte == 3) || ((u >> (shamt + 8)) == prefix);
            if (m) atomicAdd(&hist[(u >> shamt) & 255u], 1u);
        }
        __syncthreads();
        if (t == 0) {
            int cum = 0, bin;
            for (bin = 255; bin >= 0; --bin) {
                int h = (int)hist[bin];
                if (cum + h >= k) break;
                cum += h;
            }
            if (bin < 0) bin = 0;
            sh_pref = (prefix << 8) | (unsigned)bin;
            sh_k = k - cum;
        }
        __syncthreads();
        prefix = sh_pref; k = sh_k;
        __syncthreads();
    }
    unsigned T = prefix;
    if (t == 0) { cntGT = 0; eqcnt = 0; }
    __syncthreads();
    for (int i = t; i < HWSZ; i += bd) {
        unsigned u = __float_as_uint(sc[i] + sc2[i]);
        u = (u & 0x80000000u) ? ~u : (u | 0x80000000u);
        if (u > T) {
            int p = atomicAdd(&cntGT, 1);
            if (p < NPTS) g_idx[b * NPTS + p] = i;
        } else if (u == T) {
            int e = atomicAdd(&eqcnt, 1);
            if (e < 1024) eqbuf[e] = i;
        }
    }
    __syncthreads();
    if (t == 0) {
        int need = k;
        int base = cntGT;
        int ec = eqcnt; if (ec > 1024) ec = 1024;
        if (ec > need) {
            for (int a = 1; a < ec; ++a) {
                int v = eqbuf[a]; int jj = a - 1;
                while (jj >= 0 && eqbuf[jj] > v) { eqbuf[jj + 1] = eqbuf[jj]; --jj; }
                eqbuf[jj + 1] = v;
            }
        }
        for (int e = 0; e < need && e < ec && base + e < NPTS; ++e)
            g_idx[b * NPTS + base + e] = eqbuf[e];
    }
}

// ================= kernel 3: stream plane -> pool from smem (round-5 structure) =================
__global__ void __launch_bounds__(256) k3_pool(const float* __restrict__ xm,
                                               const float* __restrict__ xa) {
    extern __shared__ float sp[];
    int* s_hw = (int*)(sp + HWSZ);
    int c = blockIdx.x, b = blockIdx.y, t = threadIdx.x;

    for (int i = t; i < NPTS; i += 256) s_hw[i] = g_idx[b * NPTS + i];

    #pragma unroll
    for (int s = 0; s < 2; ++s) {
        const float* src = (s == 0 ? xm : xa) + (size_t)(b * CH + c) * HWSZ;
        __syncthreads();
        for (int i = t; i < HWSZ / 4; i += 256)
            reinterpret_cast<float4*>(sp)[i] = reinterpret_cast<const float4*>(src)[i];
        __syncthreads();

        for (int p = t; p < NPTS; p += 256) {
            int hw = s_hw[p];
            int iy = hw >> 7, ix = hw & 127;
            float sum = 0.f, mx = -CUDART_INF_F;
            if (iy >= 3 && iy <= 124 && ix >= 3 && ix <= 124) {
                const float* base = sp + (iy - 3) * WW + (ix - 3);
                #pragma unroll
                for (int dy = 0; dy < 7; ++dy) {
                    #pragma unroll
                    for (int dx = 0; dx < 7; ++dx) {
                        float v = base[dy * WW + dx];
                        sum += v; mx = fmaxf(mx, v);
                    }
                }
            } else {
                #pragma unroll
                for (int dy = -3; dy <= 3; ++dy) {
                    int yy = iy + dy; float wy = 1.f;
                    if (yy < 0) { yy = 0; wy = 0.5f; } else if (yy > 127) { yy = 127; wy = 0.5f; }
                    #pragma unroll
                    for (int dx = -3; dx <= 3; ++dx) {
                        int xx = ix + dx; float wx = wy;
                        if (xx < 0) { xx = 0; wx *= 0.5f; } else if (xx > 127) { xx = 127; wx *= 0.5f; }
                        float v = sp[yy * WW + xx] * wx;
                        sum += v; mx = fmaxf(mx, v);
                    }
                }
            }
            float r = 0.5f * (sum * (1.f / 49.f) + mx);
            if (s == 0) {
                g_vmt[(b * CH + c) * NPAD + p] = r;
            } else {
                g_vat[(b * CH + c) * NPAD + p] = r;
                g_vaux[(b * NPAD + p) * CH + c] = r;
            }
        }
    }
}

// ================= kernel 4: tensor-core (tf32 mma.sync) attention + MLP + proj =================
// smem (floats):
//  Qt [256][40]           @ 0      (10240)
//  KB 2x[8][520]          @ 10240  (8320)   ; later W1p[256][32] (8192)
//  S  [32][520] (S then P)@ 18560  (16640)  ; later Vf[32][264] (8448) + W2s[4096] @ +8448
//  VB 2x[16][264]         @ 35200  (8448)
//  Vh [32][264]           @ 43648  (8448)
#define T_QT 0
#define T_KB 10240
#define T_S  18560
#define T_VB 35200
#define T_VH 43648
#define T_TOT 52096

__global__ void __launch_bounds__(512, 1)
k4_attn(const float* __restrict__ fc1w, const float* __restrict__ fc1b,
        const float* __restrict__ fc2w, const float* __restrict__ fc2b,
        const float* __restrict__ pw,   const float* __restrict__ pb,
        float* __restrict__ out) {
    extern __shared__ float sm[];
    float* Qt = sm + T_QT;
    float* KB = sm + T_KB;
    float* S  = sm + T_S;
    float* VB = sm + T_VB;
    float* Vh = sm + T_VH;

    const int t = threadIdx.x, lane = t & 31, w = t >> 5;
    const int gid = lane >> 2, tig = lane & 3;
    const int b = blockIdx.y;
    const int r0 = blockIdx.x * 32;
    const int nrows = min(32, NPTS - r0);

    // ---- stage Q [k][r] pitch 40 (raw fp32 used as tf32) ----
    for (int idx4 = t; idx4 < 2048; idx4 += 512) {
        int k = idx4 >> 3, i4 = (idx4 & 7) * 4;
        float4 v = *reinterpret_cast<const float4*>(&g_vmt[(b * CH + k) * NPAD + r0 + i4]);
        *reinterpret_cast<float4*>(&Qt[k * 40 + i4]) = v;
    }

    // ================= GEMM1: S[32][512] = Q[32][256] * K^T, scaled 1/16 =================
    {
        float dq[2][4][4] = {};
        const int ntb = w * 4;
        // prologue: K-slice 0 (k rows 0..7, 512 m)
        #pragma unroll
        for (int ii = 0; ii < 2; ++ii) {
            int op = t + ii * 512;
            int row = op >> 7, ch = op & 127;
            cp16(&KB[row * 520 + ch * 4], &g_vat[(size_t)(b * CH + row) * NPAD + ch * 4]);
        }
        CP_COMMIT();
        for (int s = 0; s < 32; ++s) {
            if (s + 1 < 32) {
                int kbase = 8 * (s + 1);
                int bufo = ((s + 1) & 1) * 4160;
                #pragma unroll
                for (int ii = 0; ii < 2; ++ii) {
                    int op = t + ii * 512;
                    int row = op >> 7, ch = op & 127;
                    cp16(&KB[bufo + row * 520 + ch * 4],
                         &g_vat[(size_t)(b * CH + kbase + row) * NPAD + ch * 4]);
                }
                CP_COMMIT();
                CP_WAIT1();
            } else {
                CP_WAIT0();
            }
            __syncthreads();
            const uint32_t* KS  = (const uint32_t*)&KB[(s & 1) * 4160];
            const uint32_t* QtU = (const uint32_t*)Qt;
            uint32_t A[2][4];
            int ka = (8 * s + tig) * 40;
            int kb = (8 * s + tig + 4) * 40;
            #pragma unroll
            for (int mt = 0; mt < 2; ++mt) {
                int r = mt * 16 + gid;
                A[mt][0] = QtU[ka + r];
                A[mt][1] = QtU[ka + r + 8];
                A[mt][2] = QtU[kb + r];
                A[mt][3] = QtU[kb + r + 8];
            }
            #pragma unroll
            for (int j = 0; j < 4; ++j) {
                int n0 = (ntb + j) * 8 + gid;
                uint32_t B[2];
                B[0] = KS[tig * 520 + n0];
                B[1] = KS[(tig + 4) * 520 + n0];
                mma8(dq[0][j], A[0], B);
                mma8(dq[1][j], A[1], B);
            }
            __syncthreads();
        }
        #pragma unroll
        for (int mt = 0; mt < 2; ++mt) {
            #pragma unroll
            for (int j = 0; j < 4; ++j) {
                int r = mt * 16 + gid;
                int n0 = (ntb + j) * 8 + 2 * tig;
                S[r * 520 + n0]           = dq[mt][j][0] * 0.0625f;
                S[r * 520 + n0 + 1]       = dq[mt][j][1] * 0.0625f;
                S[(r + 8) * 520 + n0]     = dq[mt][j][2] * 0.0625f;
                S[(r + 8) * 520 + n0 + 1] = dq[mt][j][3] * 0.0625f;
            }
        }
        __syncthreads();
    }

    // ================= softmax rows (normalized P left in S; m>=500 zeroed) =================
    #pragma unroll
    for (int i = 0; i < 2; ++i) {
        int r = 2 * w + i;
        float mxv = -CUDART_INF_F;
        for (int m = lane; m < NPTS; m += 32) mxv = fmaxf(mxv, S[r * 520 + m]);
        #pragma unroll
        for (int o = 16; o; o >>= 1) mxv = fmaxf(mxv, __shfl_xor_sync(0xffffffffu, mxv, o));
        float sum = 0.f;
        for (int m = lane; m < NPTS; m += 32) {
            float e = __expf(S[r * 520 + m] - mxv);
            S[r * 520 + m] = e;
            sum += e;
        }
        #pragma unroll
        for (int o = 16; o; o >>= 1) sum += __shfl_xor_sync(0xffffffffu, sum, o);
        float inv = 1.f / sum;
        for (int m = lane; m < 512; m += 32) {
            float v = (m < NPTS) ? S[r * 520 + m] * inv : 0.f;
            S[r * 520 + m] = v;
        }
    }
    __syncthreads();

    // ================= GEMM2: Vh[32][256] = P[32][512] * V[512][256] =================
    {
        float dv[2][2][4] = {};
        const int ntb2 = w * 2;
        #pragma unroll
        for (int ii = 0; ii < 2; ++ii) {
            int op = t + ii * 512;
            int row = op >> 6, ch = op & 63;
            cp16(&VB[row * 264 + ch * 4], &g_vaux[(size_t)(b * NPAD + row) * CH + ch * 4]);
        }
        CP_COMMIT();
        for (int s = 0; s < 32; ++s) {
            if (s + 1 < 32) {
                int mb = 16 * (s + 1);
                int bufo = ((s + 1) & 1) * 4224;
                #pragma unroll
                for (int ii = 0; ii < 2; ++ii) {
                    int op = t + ii * 512;
                    int row = op >> 6, ch = op & 63;
                    cp16(&VB[bufo + row * 264 + ch * 4],
                         &g_vaux[(size_t)(b * NPAD + mb + row) * CH + ch * 4]);
                }
                CP_COMMIT();
                CP_WAIT1();
            } else {
                CP_WAIT0();
            }
            __syncthreads();
            const uint32_t* VS = (const uint32_t*)&VB[(s & 1) * 4224];
            const uint32_t* PU = (const uint32_t*)S;
            #pragma unroll
            for (int kk = 0; kk < 2; ++kk) {
                int k0 = 16 * s + 8 * kk;
                uint32_t A[2][4];
                #pragma unroll
                for (int mt = 0; mt < 2; ++mt) {
                    int r = mt * 16 + gid;
                    A[mt][0] = PU[r * 520 + k0 + tig];
                    A[mt][1] = PU[(r + 8) * 520 + k0 + tig];
                    A[mt][2] = PU[r * 520 + k0 + tig + 4];
                    A[mt][3] = PU[(r + 8) * 520 + k0 + tig + 4];
                }
                #pragma unroll
                for (int j = 0; j < 2; ++j) {
                    int n0 = (ntb2 + j) * 8 + gid;
                    uint32_t B[2];
                    B[0] = VS[(8 * kk + tig) * 264 + n0];
                    B[1] = VS[(8 * kk + tig + 4) * 264 + n0];
                    mma8(dv[0][j], A[0], B);
                    mma8(dv[1][j], A[1], B);
                }
            }
            __syncthreads();
        }
        #pragma unroll
        for (int mt = 0; mt < 2; ++mt) {
            #pragma unroll
            for (int j = 0; j < 2; ++j) {
                int r = mt * 16 + gid;
                int n0 = (ntb2 + j) * 8 + 2 * tig;
                Vh[r * 264 + n0]           = dv[mt][j][0];
                Vh[r * 264 + n0 + 1]       = dv[mt][j][1];
                Vh[(r + 8) * 264 + n0]     = dv[mt][j][2];
                Vh[(r + 8) * 264 + n0 + 1] = dv[mt][j][3];
            }
        }
        __syncthreads();
    }

    // ================= gated fusion MLP (fp32 exact, as before) =================
    float* W1p = KB;            // [256][32] interleaved (W1a,W1b)
    float* Vf  = S;             // [32][264] fused result (P dead)
    float* W2s = S + 8448;      // [16][256]
    for (int idx = t; idx < 4096; idx += 512) {
        int k = idx >> 4, j = idx & 15;
        float wa = fc1w[idx];
        float wb = fc1w[4096 + idx];
        float wc = fc1w[8192 + idx];
        W1p[k * 32 + 2 * j]     = wa + wc;
        W1p[k * 32 + 2 * j + 1] = wb - wc;
    }
    for (int idx = t; idx < 4096; idx += 512) W2s[idx] = fc2w[idx];
    __syncthreads();

    int jl = lane & 15, half = lane >> 4;
    float hreg[2];
    #pragma unroll
    for (int i = 0; i < 2; ++i) {
        int r = 2 * w + i;
        u64 hp = pk2(0.f, 0.f);
        int k0 = half * 128;
        #pragma unroll 4
        for (int k = k0; k < k0 + 128; ++k) {
            float vm = Qt[k * 40 + r];
            float vh = Vh[r * 264 + k];
            u64 wv = *reinterpret_cast<const u64*>(&W1p[k * 32 + 2 * jl]);
            hp = f2fma(pk2(vm, vh), wv, hp);
        }
        float hx, hy; upk2(hx, hy, hp);
        float h = hx + hy;
        h += __shfl_xor_sync(0xffffffffu, h, 16);
        h += fc1b[jl];
        hreg[i] = fmaxf(h, 0.f);
    }
    #pragma unroll
    for (int i = 0; i < 2; ++i) {
        int r = 2 * w + i;
        for (int cb = 0; cb < 256; cb += 32) {
            int c = cb + lane;
            float gg = fc2b[c];
            #pragma unroll
            for (int jj = 0; jj < 16; ++jj)
                gg += __shfl_sync(0xffffffffu, hreg[i], jj) * W2s[jj * 256 + c];
            gg = 1.f / (1.f + __expf(-gg));
            float vm = Qt[c * 40 + r];
            float vh = Vh[r * 264 + c];
            Vf[r * 264 + c] = vm + gg * (vm - vh);
        }
    }
    __syncthreads();

    // ================= GEMM3: v_inj = Vf[32][256] * proj_w[256][256]; scatter =================
    {
        float dp[2][2][4] = {};
        const int ntb3 = w * 2;
        #pragma unroll
        for (int ii = 0; ii < 2; ++ii) {
            int op = t + ii * 512;
            int row = op >> 6, ch = op & 63;
            cp16(&VB[row * 264 + ch * 4], &pw[(size_t)row * 256 + ch * 4]);
        }
        CP_COMMIT();
        for (int s = 0; s < 16; ++s) {
            if (s + 1 < 16) {
                int kbse = 16 * (s + 1);
                int bufo = ((s + 1) & 1) * 4224;
                #pragma unroll
                for (int ii = 0; ii < 2; ++ii) {
                    int op = t + ii * 512;
                    int row = op >> 6, ch = op & 63;
                    cp16(&VB[bufo + row * 264 + ch * 4],
                         &pw[(size_t)(kbse + row) * 256 + ch * 4]);
                }
                CP_COMMIT();
                CP_WAIT1();
            } else {
                CP_WAIT0();
            }
            __syncthreads();
            const uint32_t* WS = (const uint32_t*)&VB[(s & 1) * 4224];
            const uint32_t* FU = (const uint32_t*)Vf;
            #pragma unroll
            for (int kk = 0; kk < 2; ++kk) {
                int k0 = 16 * s + 8 * kk;
                uint32_t A[2][4];
                #pragma unroll
                for (int mt = 0; mt < 2; ++mt) {
                    int r = mt * 16 + gid;
                    A[mt][0] = FU[r * 264 + k0 + tig];
                    A[mt][1] = FU[(r + 8) * 264 + k0 + tig];
                    A[mt][2] = FU[r * 264 + k0 + tig + 4];
                    A[mt][3] = FU[(r + 8) * 264 + k0 + tig + 4];
                }
                #pragma unroll
                for (int j = 0; j < 2; ++j) {
                    int n0 = (ntb3 + j) * 8 + gid;
                    uint32_t B[2];
                    B[0] = WS[(8 * kk + tig) * 264 + n0];
                    B[1] = WS[(8 * kk + tig + 4) * 264 + n0];
                    mma8(dp[0][j], A[0], B);
                    mma8(dp[1][j], A[1], B);
                }
            }
            __syncthreads();
        }
        // scatter-add epilogue (indices unique per batch -> plain RMW)
        #pragma unroll
        for (int mt = 0; mt < 2; ++mt) {
            int r = mt * 16 + gid;
            int hw0 = (r < nrows)     ? g_idx[b * NPTS + r0 + r]     : -1;
            int hw1 = (r + 8 < nrows) ? g_idx[b * NPTS + r0 + r + 8] : -1;
            #pragma unroll
            for (int j = 0; j < 2; ++j) {
                int c = (ntb3 + j) * 8 + 2 * tig;
                float pb0 = pb[c], pb1 = pb[c + 1];
                if (hw0 >= 0) {
                    float* o0 = out + (size_t)(b * CH + c) * HWSZ + hw0;
                    o0[0]    += dp[mt][j][0] + pb0;
                    o0[HWSZ] += dp[mt][j][1] + pb1;
                }
                if (hw1 >= 0) {
                    float* o1 = out + (size_t)(b * CH + c) * HWSZ + hw1;
                    o1[0]    += dp[mt][j][2] + pb0;
                    o1[HWSZ] += dp[mt][j][3] + pb1;
                }
            }
        }
    }
}

// ================= launch =================
extern "C" void kernel_launch(void* const* d_in, const int* in_sizes, int n_in,
                              void* d_out, int out_size) {
    const float* xm   = (const float*)d_in[0];
    const float* xa   = (const float*)d_in[1];
    const float* sw   = (const float*)d_in[2];
    const float* fc1w = (const float*)d_in[4];
    const float* fc1b = (const float*)d_in[5];
    const float* fc2w = (const float*)d_in[6];
    const float* fc2b = (const float*)d_in[7];
    const float* pw   = (const float*)d_in[8];
    const float* pb   = (const float*)d_in[9];
    float* out = (float*)d_out;

    const int K3_SMEM = HWSZ * 4 + NPTS * 4;   // 67536 B
    const int K4_SMEM = T_TOT * 4;             // 208384 B
    cudaFuncSetAttribute(k3_pool, cudaFuncAttributeMaxDynamicSharedMemorySize, K3_SMEM);
    cudaFuncSetAttribute(k4_attn, cudaFuncAttributeMaxDynamicSharedMemorySize, K4_SMEM);

    k1_copy_score<<<dim3(512, 2), 256>>>(xm, sw, out);
    k2_topk<<<BATCH, 512>>>();
    k3_pool<<<dim3(CH, BATCH), 256, K3_SMEM>>>(xm, xa);
    k4_attn<<<dim3(16, BATCH), 512, K4_SMEM>>>(fc1w, fc1b, fc2w, fc2b, pw, pb, out);
}